// round 8
// baseline (speedup 1.0000x reference)
#include <cuda_runtime.h>
#include <cstdint>
#include <math.h>

// CTRNN B=128, N=512, T=1024, fp32. 16 independent clusters of 8 CTAs.
// Rank r owns hidden cols [r*64, r*64+64); cluster g owns batch rows [g*8,+8).
// R7: PER-WARP exchange pipeline. k-split warp w consumes exactly rank w's
// th slice -> 8 per-rank full barriers (count=1). Each warp waits only for
// its own slice, stages it itself (4xLDG.128 + 4xSTS.128 + syncwarp), and
// GEMMs independently. Own slice staged via STS at publish (no wait).
// 2 syncthreads/step; arrives from warp 0 post-sync (cumulative release).

#define T_STEPS 1024
#define BATCH   128
#define NH      512
#define DTC     0.02f

#define CL   8
#define BS   8
#define IS   64
#define NCTA 128
#define NTHR 256
#define KW   8
#define KCH  64
#define LDP  516
#define RB   80

// smem float offsets
#define OFF_J     0                            // 64*516
#define OFF_TH    (OFF_J + IS * LDP)
#define OFF_RED   (OFF_TH + BS * LDP)
#define OFF_VEL   (OFF_RED + KW * BS * RB)
#define OFF_RPART (OFF_VEL + BS * T_STEPS)     // [2][CL][BS]
#define OFF_BARS  (OFF_RPART + 2 * CL * BS)    // 8 mbarriers (8B each)
#define SMEM_FLOATS (OFF_BARS + 16)
#define SMEM_BYTES  (SMEM_FLOATS * 4)

__device__ float g_th[2][BATCH][NH];   // tanh(h) double buffer (L2 exchange)

__device__ __forceinline__ unsigned long long ffma2(unsigned long long a,
                                                    unsigned long long b,
                                                    unsigned long long c) {
    unsigned long long d;
    asm("fma.rn.f32x2 %0, %1, %2, %3;" : "=l"(d) : "l"(a), "l"(b), "l"(c));
    return d;
}

__device__ __forceinline__ float2 unpack2(unsigned long long v) {
    float2 f;
    asm("mov.b64 {%0, %1}, %2;" : "=f"(f.x), "=f"(f.y) : "l"(v));
    return f;
}

__device__ __forceinline__ float fast_tanh(float x) {
    float e = __expf(2.0f * x);
    return 1.0f - __fdividef(2.0f, e + 1.0f);
}

__device__ __forceinline__ void mbar_init(uint32_t addr, uint32_t count) {
    asm volatile("mbarrier.init.shared.b64 [%0], %1;" :: "r"(addr), "r"(count) : "memory");
}

__device__ __forceinline__ void mbar_arrive_remote(uint32_t local_addr, uint32_t target) {
    uint32_t raddr;
    asm volatile("mapa.shared::cluster.u32 %0, %1, %2;" : "=r"(raddr)
                 : "r"(local_addr), "r"(target));
    asm volatile("mbarrier.arrive.release.cluster.shared::cluster.b64 _, [%0];"
                 :: "r"(raddr) : "memory");
}

__device__ __forceinline__ void mbar_wait(uint32_t addr, uint32_t parity) {
    uint32_t done;
    asm volatile(
        "{\n\t.reg .pred p;\n\t"
        "mbarrier.try_wait.parity.acquire.cluster.shared::cta.b64 p, [%1], %2;\n\t"
        "selp.b32 %0, 1, 0, p;\n\t}"
        : "=r"(done) : "r"(addr), "r"(parity) : "memory");
    if (!done) {
        asm volatile(
            "{\n\t.reg .pred P1;\n\t"
            "WL_%=:\n\t"
            "mbarrier.try_wait.parity.acquire.cluster.shared::cta.b64 P1, [%0], %1, 0x989680;\n\t"
            "@P1 bra.uni WD_%=;\n\t"
            "bra.uni WL_%=;\n\t"
            "WD_%=:\n\t}"
            :: "r"(addr), "r"(parity) : "memory");
    }
}

__device__ __forceinline__ void st_rank0_f32(const float* local, float v) {
    uint32_t laddr = (uint32_t)__cvta_generic_to_shared((void*)local);
    uint32_t raddr;
    asm volatile("mapa.shared::cluster.u32 %0, %1, 0;" : "=r"(raddr) : "r"(laddr));
    asm volatile("st.shared::cluster.f32 [%0], %1;" :: "r"(raddr), "f"(v) : "memory");
}

extern "C" __global__ void __launch_bounds__(NTHR, 1) __cluster_dims__(CL, 1, 1)
ctrnn_r7_kernel(const float* __restrict__ vel,
                const float* __restrict__ J,
                const float* __restrict__ Bmat,
                const float* __restrict__ Wro,
                float* __restrict__ out) {
    extern __shared__ float smem[];
    float* J_s   = smem + OFF_J;
    float* th_s  = smem + OFF_TH;
    float* red   = smem + OFF_RED;
    float* vel_s = smem + OFF_VEL;
    float* rpart = smem + OFF_RPART;

    const uint32_t bars = (uint32_t)__cvta_generic_to_shared(smem + OFF_BARS);
    // full[c] @ bars + c*8, count = 1 (single releasing arrive per step)

    const int tid  = threadIdx.x;
    const int rank = blockIdx.x & (CL - 1);
    const int grp  = blockIdx.x / CL;
    const int b0   = grp * BS;
    const int i0   = rank * IS;

    // One-time loads.
    for (int k4 = tid; k4 < IS * NH / 4; k4 += NTHR) {
        int idx = k4 * 4, r = idx >> 9, c = idx & 511;
        *reinterpret_cast<float4*>(J_s + r * LDP + c) =
            *reinterpret_cast<const float4*>(J + (size_t)(i0 + r) * NH + c);
    }
    for (int k4 = tid; k4 < BS * T_STEPS / 4; k4 += NTHR) {
        int idx = k4 * 4, r = idx >> 10, c = idx & 1023;
        *reinterpret_cast<float4*>(vel_s + r * T_STEPS + c) =
            *reinterpret_cast<const float4*>(vel + (size_t)(b0 + r) * T_STEPS + c);
    }
    for (int k4 = tid; k4 < BS * NH / 4; k4 += NTHR) {      // th(t=0) = 0
        int idx = k4 * 4, r = idx >> 9, c = idx & 511;
        *reinterpret_cast<float4*>(th_s + r * LDP + c) = make_float4(0.f, 0.f, 0.f, 0.f);
    }
    if (tid < CL) mbar_init(bars + tid * 8, 1);
    __syncthreads();
    asm volatile("barrier.cluster.arrive.aligned;" ::: "memory");
    asm volatile("barrier.cluster.wait.aligned;" ::: "memory");

    const int w = tid >> 5, lane = tid & 31;
    const int bg = lane & 1, ig = lane >> 1;
    const int kbase = w * KCH;               // warp w <-> rank w's slice

    // Reduce-phase: warp w owns batch row b=w; i = lane, lane+32.
    const float bm1 = Bmat[i0 + lane];
    const float bm2 = Bmat[i0 + lane + 32];
    const float wr1 = Wro[i0 + lane];
    const float wr2 = Wro[i0 + lane + 32];
    float h1 = 0.f, h2 = 0.f;

    for (int t = 0; t < T_STEPS; ++t) {
        // ---- per-warp wait + stage of slice w (skip own slice & t=0) ----
        if (t > 0 && w != rank) {
            mbar_wait(bars + w * 8, (uint32_t)(t - 1) & 1u);
            const float* src = &g_th[(t - 1) & 1][b0][0];
            #pragma unroll
            for (int q = 0; q < 4; ++q) {
                int idx = lane + 32 * q;          // 0..127
                int row = idx >> 4, col = kbase + (idx & 15) * 4;
                float4 v4 = __ldcg(reinterpret_cast<const float4*>(src + (size_t)row * NH + col));
                *reinterpret_cast<float4*>(th_s + row * LDP + col) = v4;
            }
            __syncwarp();
        }

        // ---- GEMM: red[w][b][i] = sum_{j in slice w} th[b][j] * J[i][j] ----
        unsigned long long acc[4][4];
        #pragma unroll
        for (int u = 0; u < 4; ++u)
            #pragma unroll
            for (int v = 0; v < 4; ++v) acc[u][v] = 0ull;

        #pragma unroll
        for (int jt = 0; jt < KCH; jt += 4) {
            const int j = kbase + jt;
            ulonglong2 av[4], bv[4];
            #pragma unroll
            for (int u = 0; u < 4; ++u)
                av[u] = *reinterpret_cast<const ulonglong2*>(th_s + (bg + 2 * u) * LDP + j);
            #pragma unroll
            for (int v = 0; v < 4; ++v)
                bv[v] = *reinterpret_cast<const ulonglong2*>(J_s + (ig + 16 * v) * LDP + j);
            #pragma unroll
            for (int u = 0; u < 4; ++u)
                #pragma unroll
                for (int v = 0; v < 4; ++v) {
                    acc[u][v] = ffma2(av[u].x, bv[v].x, acc[u][v]);
                    acc[u][v] = ffma2(av[u].y, bv[v].y, acc[u][v]);
                }
        }
        #pragma unroll
        for (int u = 0; u < 4; ++u)
            #pragma unroll
            for (int v = 0; v < 4; ++v) {
                float2 f2 = unpack2(acc[u][v]);
                red[w * (BS * RB) + (bg + 2 * u) * RB + (ig + 16 * v)] = f2.x + f2.y;
            }
        __syncthreads();                                   // SYNC A

        // ---- reduce + h update + tanh;  rank0 lagged out write ----
        if (rank == 0 && t > 0 && tid < BS) {
            const float* rp = rpart + ((t - 1) & 1) * CL * BS;
            float s = 0.f;
            #pragma unroll
            for (int r = 0; r < CL; ++r) s += rp[r * BS + tid];
            out[(size_t)(b0 + tid) * T_STEPS + (t - 1)] = s;
        }

        float s1 = 0.f, s2 = 0.f;
        #pragma unroll
        for (int k = 0; k < KW; ++k) {
            s1 += red[k * (BS * RB) + w * RB + lane];
            s2 += red[k * (BS * RB) + w * RB + lane + 32];
        }
        const float vt = vel_s[w * T_STEPS + t];
        h1 = h1 * (1.0f - DTC) + DTC * (s1 + vt * bm1);
        h2 = h2 * (1.0f - DTC) + DTC * (s2 + vt * bm2);
        const float th1 = fast_tanh(h1);
        const float th2 = fast_tanh(h2);

        // ---- publish ----
        // Own slice direct to th_s (consumed by warp `rank` next step).
        th_s[w * LDP + i0 + lane]      = th1;
        th_s[w * LDP + i0 + lane + 32] = th2;
        if (t < T_STEPS - 1) {
            __stcg(&g_th[t & 1][b0 + w][i0 + lane], th1);
            __stcg(&g_th[t & 1][b0 + w][i0 + lane + 32], th2);
        }
        // Readout partial for row w.
        float c = th1 * wr1 + th2 * wr2;
        #pragma unroll
        for (int off = 16; off > 0; off >>= 1)
            c += __shfl_xor_sync(0xffffffffu, c, off);
        if (lane == 0)
            st_rank0_f32(rpart + (t & 1) * CL * BS + rank * BS + w, c);

        __syncthreads();                                   // SYNC B
        // Single releasing arrive per peer (cumulative over SYNC B).
        if (t < T_STEPS - 1 && w == 0 && lane < CL && lane != rank)
            mbar_arrive_remote(bars + rank * 8, (uint32_t)lane);
    }

    // Final-step readout flush.
    asm volatile("barrier.cluster.arrive.aligned;" ::: "memory");
    asm volatile("barrier.cluster.wait.aligned;" ::: "memory");
    if (rank == 0 && tid < BS) {
        const float* rp = rpart + ((T_STEPS - 1) & 1) * CL * BS;
        float s = 0.f;
        #pragma unroll
        for (int r = 0; r < CL; ++r) s += rp[r * BS + tid];
        out[(size_t)(b0 + tid) * T_STEPS + (T_STEPS - 1)] = s;
    }
}

extern "C" void kernel_launch(void* const* d_in, const int* in_sizes, int n_in,
                              void* d_out, int out_size) {
    const float* vel  = (const float*)d_in[0];   // [128,1024,1]
    const float* J    = (const float*)d_in[1];   // [512,512]
    const float* Bmat = (const float*)d_in[2];   // [512,1]
    const float* Wro  = (const float*)d_in[3];   // [1,512]
    float* out = (float*)d_out;                  // [128,1024,1]

    cudaFuncSetAttribute(ctrnn_r7_kernel,
                         cudaFuncAttributeMaxDynamicSharedMemorySize, SMEM_BYTES);
    ctrnn_r7_kernel<<<NCTA, NTHR, SMEM_BYTES>>>(vel, J, Bmat, Wro, out);
}

// round 9
// speedup vs baseline: 1.3509x; 1.3509x over previous
#include <cuda_runtime.h>
#include <cstdint>
#include <math.h>

// CTRNN B=128, N=512, T=1024, fp32.
// R8: 256 CTAs (16 batch groups x 16 hidden ranks, IS=32), NO clusters.
// 2 CTAs/SM co-residency: while one CTA stalls on its exchange chain, the
// co-resident CTA (independent batch group) computes. Sync = point-to-point
// global flags (monotonic across graph replays: base = own flag at start).
// Warp w consumes ranks {2w, 2w+1}: polls 2 flags, stages its own j-chunk,
// GEMMs with no intra-CTA sync before SYNC A. FFMA2 throughout.

#define T_STEPS 1024
#define BATCH   128
#define NH      512
#define DTC     0.02f

#define NR   16                 // hidden ranks (IS = 32)
#define NG   16                 // batch groups (BS = 8)
#define BS   8
#define IS   32
#define NCTA (NG * NR)          // 256
#define NTHR 256
#define KW   8                  // j-chunks, one per warp (KCH = 64)
#define KCH  64
#define LDP  516
#define RB   40                 // red row pad

// smem float offsets
#define OFF_J   0                          // 32 x 516 = 16512
#define OFF_TH  (OFF_J + IS * LDP)         // 8 x 516  -> 20640
#define OFF_RED (OFF_TH + BS * LDP)        // 8 x 8 x 40 -> 23200
#define SMEM_FLOATS (OFF_RED + KW * BS * RB)
#define SMEM_BYTES  (SMEM_FLOATS * 4)      // 92800 B -> 2 CTAs/SM

__device__ float g_th[2][BATCH][NH];        // tanh(h) double buffer (L2)
__device__ float g_part[2][NG][NR][BS];     // readout partials
__device__ int   g_flag[NG][NR][32];        // 128B-strided step flags

__device__ __forceinline__ unsigned long long ffma2(unsigned long long a,
                                                    unsigned long long b,
                                                    unsigned long long c) {
    unsigned long long d;
    asm("fma.rn.f32x2 %0, %1, %2, %3;" : "=l"(d) : "l"(a), "l"(b), "l"(c));
    return d;
}

__device__ __forceinline__ float2 unpack2(unsigned long long v) {
    float2 f;
    asm("mov.b64 {%0, %1}, %2;" : "=f"(f.x), "=f"(f.y) : "l"(v));
    return f;
}

__device__ __forceinline__ float fast_tanh(float x) {
    float e = __expf(2.0f * x);
    return 1.0f - __fdividef(2.0f, e + 1.0f);
}

__device__ __forceinline__ int ld_acq(const int* p) {
    int v;
    asm volatile("ld.acquire.gpu.global.s32 %0, [%1];" : "=r"(v) : "l"(p) : "memory");
    return v;
}

__device__ __forceinline__ void st_rlx(int* p, int v) {
    asm volatile("st.relaxed.gpu.global.s32 [%0], %1;" :: "l"(p), "r"(v) : "memory");
}

extern "C" __global__ void __launch_bounds__(NTHR, 2)
ctrnn_r8_kernel(const float* __restrict__ vel,
                const float* __restrict__ J,
                const float* __restrict__ Bmat,
                const float* __restrict__ Wro,
                float* __restrict__ out) {
    extern __shared__ float smem[];
    float* J_s  = smem + OFF_J;
    float* th_s = smem + OFF_TH;
    float* red  = smem + OFF_RED;   // red[k][b][i] @ k*(BS*RB) + b*RB + i

    const int tid  = threadIdx.x;
    const int rank = blockIdx.x & (NR - 1);
    const int grp  = blockIdx.x >> 4;
    const int b0   = grp * BS;
    const int i0   = rank * IS;

    // One-time: J slice [IS x NH] into padded smem; zero th_s (tanh(0)=0).
    for (int k4 = tid; k4 < IS * NH / 4; k4 += NTHR) {
        int idx = k4 * 4, r = idx >> 9, c = idx & 511;
        *reinterpret_cast<float4*>(J_s + r * LDP + c) =
            *reinterpret_cast<const float4*>(J + (size_t)(i0 + r) * NH + c);
    }
    for (int k4 = tid; k4 < BS * NH / 4; k4 += NTHR) {
        int idx = k4 * 4, r = idx >> 9, c = idx & 511;
        *reinterpret_cast<float4*>(th_s + r * LDP + c) = make_float4(0.f, 0.f, 0.f, 0.f);
    }
    // Monotonic flag base (all flags equal at launch; deterministic behavior).
    const int base = __ldcg(&g_flag[grp][rank][0]);
    __syncthreads();

    const int w = tid >> 5, lane = tid & 31;
    const int bg = lane & 3, ig = lane >> 2;      // GEMM tile coords
    const int kbase = w * KCH;
    const int b = tid >> 5, i = lane;             // reduce ownership (b==w)
    const float bmv = Bmat[i0 + i];
    const float wrv = Wro[i0 + i];
    const int* fA = &g_flag[grp][2 * w][0];
    const int* fB = &g_flag[grp][2 * w + 1][0];
    float h = 0.f;

    for (int t = 0; t < T_STEPS; ++t) {
        const int p = t & 1;

        // Prefetch vel (const input; consumed after SYNC A).
        const float vt = vel[(size_t)(b0 + b) * T_STEPS + t];

        // ---- per-warp poll + stage of j-chunk [64w, 64w+64) ----
        if (t > 0) {
            const int tgt = base + t;
            while (ld_acq(fA) < tgt) { }
            while (ld_acq(fB) < tgt) { }
            const float* src = &g_th[(t - 1) & 1][b0][0];
            #pragma unroll
            for (int q = 0; q < 4; ++q) {
                int idx = lane + 32 * q;                  // 0..127
                int row = idx >> 4, col = kbase + (idx & 15) * 4;
                float4 v4 = __ldcg(reinterpret_cast<const float4*>(
                    src + (size_t)row * NH + col));
                *reinterpret_cast<float4*>(th_s + row * LDP + col) = v4;
            }
            __syncwarp();
        }

        // ---- GEMM: red[w][b][i] = sum_{j in chunk w} th[b][j] * J[i][j]
        // per-lane tile: b in {bg, bg+4}, i in {ig, ig+8, ig+16, ig+24}.
        unsigned long long acc[2][4];
        #pragma unroll
        for (int u = 0; u < 2; ++u)
            #pragma unroll
            for (int v = 0; v < 4; ++v) acc[u][v] = 0ull;

        #pragma unroll
        for (int jt = 0; jt < KCH; jt += 4) {
            const int j = kbase + jt;
            ulonglong2 av[2], bv[4];
            #pragma unroll
            for (int u = 0; u < 2; ++u)
                av[u] = *reinterpret_cast<const ulonglong2*>(th_s + (bg + 4 * u) * LDP + j);
            #pragma unroll
            for (int v = 0; v < 4; ++v)
                bv[v] = *reinterpret_cast<const ulonglong2*>(J_s + (ig + 8 * v) * LDP + j);
            #pragma unroll
            for (int u = 0; u < 2; ++u)
                #pragma unroll
                for (int v = 0; v < 4; ++v) {
                    acc[u][v] = ffma2(av[u].x, bv[v].x, acc[u][v]);
                    acc[u][v] = ffma2(av[u].y, bv[v].y, acc[u][v]);
                }
        }
        #pragma unroll
        for (int u = 0; u < 2; ++u)
            #pragma unroll
            for (int v = 0; v < 4; ++v) {
                float2 f2 = unpack2(acc[u][v]);
                red[w * (BS * RB) + (bg + 4 * u) * RB + (ig + 8 * v)] = f2.x + f2.y;
            }
        __syncthreads();                                  // SYNC A

        // ---- lagged out write (rank 0 only; peers' t-1 partials visible
        //      via this CTA's collective acquires + SYNC A) ----
        if (rank == 0 && t > 0 && tid < BS) {
            float s = 0.f;
            #pragma unroll
            for (int r = 0; r < NR; ++r)
                s += __ldcg(&g_part[(t - 1) & 1][grp][r][tid]);
            out[(size_t)(b0 + tid) * T_STEPS + (t - 1)] = s;
        }

        // ---- k-reduce + h update + tanh ----
        float s = 0.f;
        #pragma unroll
        for (int k = 0; k < KW; ++k) s += red[k * (BS * RB) + b * RB + i];
        h = h * (1.0f - DTC) + DTC * (s + vt * bmv);
        const float th = fast_tanh(h);

        // ---- publish ----
        if (t < T_STEPS - 1)
            __stcg(&g_th[p][b0 + b][i0 + i], th);
        float c = th * wrv;
        #pragma unroll
        for (int off = 16; off > 0; off >>= 1)
            c += __shfl_xor_sync(0xffffffffu, c, off);
        if (lane == 0)
            __stcg(&g_part[p][grp][rank][b], c);

        __threadfence();                                  // gpu-scope release
        __syncthreads();                                  // SYNC B
        if (tid == 0) st_rlx(&g_flag[grp][rank][0], base + t + 1);
    }

    // ---- final-step readout (rank 0): wait all ranks' last flag ----
    if (rank == 0) {
        if (tid < NR) {
            const int tgt = base + T_STEPS;
            while (ld_acq(&g_flag[grp][tid][0]) < tgt) { }
        }
        __syncthreads();
        if (tid < BS) {
            float s = 0.f;
            #pragma unroll
            for (int r = 0; r < NR; ++r)
                s += __ldcg(&g_part[(T_STEPS - 1) & 1][grp][r][tid]);
            out[(size_t)(b0 + tid) * T_STEPS + (T_STEPS - 1)] = s;
        }
    }
}

extern "C" void kernel_launch(void* const* d_in, const int* in_sizes, int n_in,
                              void* d_out, int out_size) {
    const float* vel  = (const float*)d_in[0];   // [128,1024,1]
    const float* J    = (const float*)d_in[1];   // [512,512]
    const float* Bmat = (const float*)d_in[2];   // [512,1]
    const float* Wro  = (const float*)d_in[3];   // [1,512]
    float* out = (float*)d_out;                  // [128,1024,1]

    cudaFuncSetAttribute(ctrnn_r8_kernel,
                         cudaFuncAttributeMaxDynamicSharedMemorySize, SMEM_BYTES);
    ctrnn_r8_kernel<<<NCTA, NTHR, SMEM_BYTES>>>(vel, J, Bmat, Wro, out);
}

// round 10
// speedup vs baseline: 1.3710x; 1.0149x over previous
#include <cuda_runtime.h>
#include <cstdint>
#include <math.h>

// CTRNN B=128, N=512, T=1024, fp32.
// R9: R8 (256 CTAs = 16 groups x 16 ranks, 2 CTAs/SM co-residency, per-warp
// j-chunk exchange) + warp-granular publish: per-rank warp-publish COUNTERS
// (8 adds/step), warp-level fence, double-buffered red -> ONE syncthreads
// per step, no CTA-wide publish coupling, no per-thread threadfence.

#define T_STEPS 1024
#define BATCH   128
#define NH      512
#define DTC     0.02f

#define NR   16                 // hidden ranks (IS = 32)
#define NG   16                 // batch groups (BS = 8)
#define BS   8
#define IS   32
#define NCTA (NG * NR)          // 256
#define NTHR 256
#define KW   8                  // j-chunks, one per warp (KCH = 64)
#define KCH  64
#define LDP  516
#define RB   40                 // red row pad

// smem float offsets
#define OFF_J   0                          // 32 x 516 = 16512
#define OFF_TH  (OFF_J + IS * LDP)         // 8 x 516  -> 20640
#define OFF_RED (OFF_TH + BS * LDP)        // 2 x 8 x 8 x 40
#define SMEM_FLOATS (OFF_RED + 2 * KW * BS * RB)
#define SMEM_BYTES  (SMEM_FLOATS * 4)      // 103040 B -> 2 CTAs/SM

__device__ float g_th[2][BATCH][NH];        // tanh(h) double buffer (L2)
__device__ float g_part[2][NG][NR][BS];     // readout partials
__device__ int   g_cnt[NG][NR][32];         // 128B-strided warp-publish counters

__device__ __forceinline__ unsigned long long ffma2(unsigned long long a,
                                                    unsigned long long b,
                                                    unsigned long long c) {
    unsigned long long d;
    asm("fma.rn.f32x2 %0, %1, %2, %3;" : "=l"(d) : "l"(a), "l"(b), "l"(c));
    return d;
}

__device__ __forceinline__ float2 unpack2(unsigned long long v) {
    float2 f;
    asm("mov.b64 {%0, %1}, %2;" : "=f"(f.x), "=f"(f.y) : "l"(v));
    return f;
}

__device__ __forceinline__ float fast_tanh(float x) {
    float e = __expf(2.0f * x);
    return 1.0f - __fdividef(2.0f, e + 1.0f);
}

__device__ __forceinline__ int ld_acq(const int* p) {
    int v;
    asm volatile("ld.acquire.gpu.global.s32 %0, [%1];" : "=r"(v) : "l"(p) : "memory");
    return v;
}

__device__ __forceinline__ void red_add_gpu(int* p, int v) {
    asm volatile("red.relaxed.gpu.global.add.s32 [%0], %1;" :: "l"(p), "r"(v) : "memory");
}

__device__ __forceinline__ void fence_gpu() {
    asm volatile("fence.acq_rel.gpu;" ::: "memory");
}

extern "C" __global__ void __launch_bounds__(NTHR, 2)
ctrnn_r9_kernel(const float* __restrict__ vel,
                const float* __restrict__ J,
                const float* __restrict__ Bmat,
                const float* __restrict__ Wro,
                float* __restrict__ out) {
    extern __shared__ float smem[];
    float* J_s  = smem + OFF_J;
    float* th_s = smem + OFF_TH;
    float* red  = smem + OFF_RED;   // [2][KW][BS][RB]

    const int tid  = threadIdx.x;
    const int rank = blockIdx.x & (NR - 1);
    const int grp  = blockIdx.x >> 4;
    const int b0   = grp * BS;
    const int i0   = rank * IS;

    // One-time: J slice [IS x NH] into padded smem; zero th_s (tanh(0)=0).
    for (int k4 = tid; k4 < IS * NH / 4; k4 += NTHR) {
        int idx = k4 * 4, r = idx >> 9, c = idx & 511;
        *reinterpret_cast<float4*>(J_s + r * LDP + c) =
            *reinterpret_cast<const float4*>(J + (size_t)(i0 + r) * NH + c);
    }
    for (int k4 = tid; k4 < BS * NH / 4; k4 += NTHR) {
        int idx = k4 * 4, r = idx >> 9, c = idx & 511;
        *reinterpret_cast<float4*>(th_s + r * LDP + c) = make_float4(0.f, 0.f, 0.f, 0.f);
    }
    // Monotonic counter base (all counters equal at every launch boundary).
    const int base = __ldcg(&g_cnt[grp][rank][0]);
    __syncthreads();

    const int w = tid >> 5, lane = tid & 31;
    const int bg = lane & 3, ig = lane >> 2;      // GEMM tile coords
    const int kbase = w * KCH;
    const int b = w, i = lane;                    // reduce/publish ownership
    const float bmv = Bmat[i0 + i];
    const float wrv = Wro[i0 + i];
    const int* fA = &g_cnt[grp][2 * w][0];
    const int* fB = &g_cnt[grp][2 * w + 1][0];
    int* fOwn = &g_cnt[grp][rank][0];
    float h = 0.f;

    for (int t = 0; t < T_STEPS; ++t) {
        const int p = t & 1;
        float* redw = red + p * (KW * BS * RB);

        // Prefetch vel (const input; consumed after SYNC A).
        const float vt = vel[(size_t)(b0 + b) * T_STEPS + t];

        // ---- per-warp poll (ranks 2w, 2w+1 complete step t-1) + stage ----
        if (t > 0) {
            const int tgt = base + 8 * t;
            while (ld_acq(fA) < tgt) { }
            while (ld_acq(fB) < tgt) { }
            const float* src = &g_th[(t - 1) & 1][b0][0];
            #pragma unroll
            for (int q = 0; q < 4; ++q) {
                int idx = lane + 32 * q;                  // 0..127
                int row = idx >> 4, col = kbase + (idx & 15) * 4;
                float4 v4 = __ldcg(reinterpret_cast<const float4*>(
                    src + (size_t)row * NH + col));
                *reinterpret_cast<float4*>(th_s + row * LDP + col) = v4;
            }
            __syncwarp();
        }

        // ---- GEMM: redw[w][b][i] = sum_{j in chunk w} th[b][j] * J[i][j]
        unsigned long long acc[2][4];
        #pragma unroll
        for (int u = 0; u < 2; ++u)
            #pragma unroll
            for (int v = 0; v < 4; ++v) acc[u][v] = 0ull;

        #pragma unroll
        for (int jt = 0; jt < KCH; jt += 4) {
            const int j = kbase + jt;
            ulonglong2 av[2], bv[4];
            #pragma unroll
            for (int u = 0; u < 2; ++u)
                av[u] = *reinterpret_cast<const ulonglong2*>(th_s + (bg + 4 * u) * LDP + j);
            #pragma unroll
            for (int v = 0; v < 4; ++v)
                bv[v] = *reinterpret_cast<const ulonglong2*>(J_s + (ig + 8 * v) * LDP + j);
            #pragma unroll
            for (int u = 0; u < 2; ++u)
                #pragma unroll
                for (int v = 0; v < 4; ++v) {
                    acc[u][v] = ffma2(av[u].x, bv[v].x, acc[u][v]);
                    acc[u][v] = ffma2(av[u].y, bv[v].y, acc[u][v]);
                }
        }
        #pragma unroll
        for (int u = 0; u < 2; ++u)
            #pragma unroll
            for (int v = 0; v < 4; ++v) {
                float2 f2 = unpack2(acc[u][v]);
                redw[w * (BS * RB) + (bg + 4 * u) * RB + (ig + 8 * v)] = f2.x + f2.y;
            }
        __syncthreads();                                  // the ONE barrier

        // ---- lagged out write (rank 0; all ranks' t-1 parts visible via
        //      this CTA's collective acquires + the barrier) ----
        if (rank == 0 && t > 0 && tid < BS) {
            float s = 0.f;
            #pragma unroll
            for (int r = 0; r < NR; ++r)
                s += __ldcg(&g_part[(t - 1) & 1][grp][r][tid]);
            out[(size_t)(b0 + tid) * T_STEPS + (t - 1)] = s;
        }

        // ---- k-reduce + h update + tanh ----
        float s = 0.f;
        #pragma unroll
        for (int k = 0; k < KW; ++k) s += redw[k * (BS * RB) + b * RB + i];
        h = h * (1.0f - DTC) + DTC * (s + vt * bmv);
        const float th = fast_tanh(h);

        // ---- warp-granular publish: row b=w is entirely this warp's ----
        if (t < T_STEPS - 1)
            __stcg(&g_th[p][b0 + b][i0 + i], th);
        float c = th * wrv;
        #pragma unroll
        for (int off = 16; off > 0; off >>= 1)
            c += __shfl_xor_sync(0xffffffffu, c, off);
        if (lane == 0)
            __stcg(&g_part[p][grp][rank][b], c);

        __syncwarp();
        fence_gpu();                                      // warp-level release
        if (lane == 0) red_add_gpu(fOwn, 1);
    }

    // ---- final-step readout (rank 0): wait all ranks' step-1024 counts ----
    if (rank == 0) {
        if (tid < NR) {
            const int tgt = base + 8 * T_STEPS;
            while (ld_acq(&g_cnt[grp][tid][0]) < tgt) { }
        }
        __syncthreads();
        if (tid < BS) {
            float s = 0.f;
            #pragma unroll
            for (int r = 0; r < NR; ++r)
                s += __ldcg(&g_part[(T_STEPS - 1) & 1][grp][r][tid]);
            out[(size_t)(b0 + tid) * T_STEPS + (T_STEPS - 1)] = s;
        }
    }
}

extern "C" void kernel_launch(void* const* d_in, const int* in_sizes, int n_in,
                              void* d_out, int out_size) {
    const float* vel  = (const float*)d_in[0];   // [128,1024,1]
    const float* J    = (const float*)d_in[1];   // [512,512]
    const float* Bmat = (const float*)d_in[2];   // [512,1]
    const float* Wro  = (const float*)d_in[3];   // [1,512]
    float* out = (float*)d_out;                  // [128,1024,1]

    cudaFuncSetAttribute(ctrnn_r9_kernel,
                         cudaFuncAttributeMaxDynamicSharedMemorySize, SMEM_BYTES);
    ctrnn_r9_kernel<<<NCTA, NTHR, SMEM_BYTES>>>(vel, J, Bmat, Wro, out);
}

// round 11
// speedup vs baseline: 1.4082x; 1.0272x over previous
#include <cuda_runtime.h>
#include <cstdint>
#include <math.h>

// CTRNN B=128, N=512, T=1024, fp32.
// R10 = R9 (256 CTAs = 16 groups x 16 ranks, 2 CTAs/SM, per-warp j-chunk
// exchange, warp-granular counters, ONE syncthreads/step) with critical-path
// surgery: readout partial moved after release; out-writer rotates across
// ranks (lag 2, quad-buffered g_part) killing the rank0 straggler; poll/stage
// interleaved; post-loop release round + flush for the last 2 columns.

#define T_STEPS 1024
#define BATCH   128
#define NH      512
#define DTC     0.02f

#define NR   16                 // hidden ranks (IS = 32)
#define NG   16                 // batch groups (BS = 8)
#define BS   8
#define IS   32
#define NCTA (NG * NR)          // 256
#define NTHR 256
#define KW   8                  // j-chunks, one per warp (KCH = 64)
#define KCH  64
#define LDP  516
#define RB   40                 // red row pad

// smem float offsets
#define OFF_J   0                          // 32 x 516
#define OFF_TH  (OFF_J + IS * LDP)         // 8 x 516
#define OFF_RED (OFF_TH + BS * LDP)        // [2][KW][BS][RB]
#define SMEM_FLOATS (OFF_RED + 2 * KW * BS * RB)
#define SMEM_BYTES  (SMEM_FLOATS * 4)      // 103040 B -> 2 CTAs/SM

__device__ float g_th[2][BATCH][NH];        // tanh(h) double buffer (L2)
__device__ float g_part[4][NG][NR][BS];     // readout partials, quad buffer
__device__ int   g_cnt[NG][NR][32];         // 128B-strided warp-publish counters

__device__ __forceinline__ unsigned long long ffma2(unsigned long long a,
                                                    unsigned long long b,
                                                    unsigned long long c) {
    unsigned long long d;
    asm("fma.rn.f32x2 %0, %1, %2, %3;" : "=l"(d) : "l"(a), "l"(b), "l"(c));
    return d;
}

__device__ __forceinline__ float2 unpack2(unsigned long long v) {
    float2 f;
    asm("mov.b64 {%0, %1}, %2;" : "=f"(f.x), "=f"(f.y) : "l"(v));
    return f;
}

__device__ __forceinline__ float fast_tanh(float x) {
    float e = __expf(2.0f * x);
    return 1.0f - __fdividef(2.0f, e + 1.0f);
}

__device__ __forceinline__ int ld_acq(const int* p) {
    int v;
    asm volatile("ld.acquire.gpu.global.s32 %0, [%1];" : "=r"(v) : "l"(p) : "memory");
    return v;
}

__device__ __forceinline__ void red_add_gpu(int* p, int v) {
    asm volatile("red.relaxed.gpu.global.add.s32 [%0], %1;" :: "l"(p), "r"(v) : "memory");
}

__device__ __forceinline__ void fence_gpu() {
    asm volatile("fence.acq_rel.gpu;" ::: "memory");
}

extern "C" __global__ void __launch_bounds__(NTHR, 2)
ctrnn_r10_kernel(const float* __restrict__ vel,
                 const float* __restrict__ J,
                 const float* __restrict__ Bmat,
                 const float* __restrict__ Wro,
                 float* __restrict__ out) {
    extern __shared__ float smem[];
    float* J_s  = smem + OFF_J;
    float* th_s = smem + OFF_TH;
    float* red  = smem + OFF_RED;   // [2][KW][BS][RB]

    const int tid  = threadIdx.x;
    const int rank = blockIdx.x & (NR - 1);
    const int grp  = blockIdx.x >> 4;
    const int b0   = grp * BS;
    const int i0   = rank * IS;

    // One-time: J slice [IS x NH] into padded smem; zero th_s (tanh(0)=0).
    for (int k4 = tid; k4 < IS * NH / 4; k4 += NTHR) {
        int idx = k4 * 4, r = idx >> 9, c = idx & 511;
        *reinterpret_cast<float4*>(J_s + r * LDP + c) =
            *reinterpret_cast<const float4*>(J + (size_t)(i0 + r) * NH + c);
    }
    for (int k4 = tid; k4 < BS * NH / 4; k4 += NTHR) {
        int idx = k4 * 4, r = idx >> 9, c = idx & 511;
        *reinterpret_cast<float4*>(th_s + r * LDP + c) = make_float4(0.f, 0.f, 0.f, 0.f);
    }
    // Monotonic counter base (all counters equal at every launch boundary).
    const int base = __ldcg(&g_cnt[grp][rank][0]);
    __syncthreads();

    const int w = tid >> 5, lane = tid & 31;
    const int bg = lane & 3, ig = lane >> 2;      // GEMM tile coords
    const int kbase = w * KCH;
    const int b = w, i = lane;                    // reduce/publish ownership
    const float bmv = Bmat[i0 + i];
    const float wrv = Wro[i0 + i];
    const int* fA = &g_cnt[grp][2 * w][0];
    const int* fB = &g_cnt[grp][2 * w + 1][0];
    int* fOwn = &g_cnt[grp][rank][0];
    float h = 0.f;

    for (int t = 0; t < T_STEPS; ++t) {
        const int p = t & 1;
        float* redw = red + p * (KW * BS * RB);

        // Prefetch vel (consumed after the barrier).
        const float vt = vel[(size_t)(b0 + b) * T_STEPS + t];

        // ---- interleaved per-warp poll + stage of j-chunk [64w, 64w+64) ----
        if (t > 0) {
            const int tgt = base + 8 * t;
            const float* src = &g_th[(t - 1) & 1][b0][0];
            while (ld_acq(fA) < tgt) { }
            float4 vA[2];
            #pragma unroll
            for (int q = 0; q < 2; ++q) {        // rank 2w's 32 j's
                int idx = lane + 32 * q;         // 0..63
                int row = idx >> 3, col = kbase + (idx & 7) * 4;
                vA[q] = __ldcg(reinterpret_cast<const float4*>(src + (size_t)row * NH + col));
            }
            while (ld_acq(fB) < tgt) { }         // overlaps vA's L2 latency
            float4 vB[2];
            #pragma unroll
            for (int q = 0; q < 2; ++q) {        // rank 2w+1's 32 j's
                int idx = lane + 32 * q;
                int row = idx >> 3, col = kbase + 32 + (idx & 7) * 4;
                vB[q] = __ldcg(reinterpret_cast<const float4*>(src + (size_t)row * NH + col));
            }
            #pragma unroll
            for (int q = 0; q < 2; ++q) {
                int idx = lane + 32 * q;
                int row = idx >> 3, colA = kbase + (idx & 7) * 4;
                *reinterpret_cast<float4*>(th_s + row * LDP + colA) = vA[q];
                *reinterpret_cast<float4*>(th_s + row * LDP + colA + 32) = vB[q];
            }
            __syncwarp();
        }

        // ---- GEMM: redw[w][b][i] = sum_{j in chunk w} th[b][j] * J[i][j]
        unsigned long long acc[2][4];
        #pragma unroll
        for (int u = 0; u < 2; ++u)
            #pragma unroll
            for (int v = 0; v < 4; ++v) acc[u][v] = 0ull;

        #pragma unroll
        for (int jt = 0; jt < KCH; jt += 4) {
            const int j = kbase + jt;
            ulonglong2 av[2], bv[4];
            #pragma unroll
            for (int u = 0; u < 2; ++u)
                av[u] = *reinterpret_cast<const ulonglong2*>(th_s + (bg + 4 * u) * LDP + j);
            #pragma unroll
            for (int v = 0; v < 4; ++v)
                bv[v] = *reinterpret_cast<const ulonglong2*>(J_s + (ig + 8 * v) * LDP + j);
            #pragma unroll
            for (int u = 0; u < 2; ++u)
                #pragma unroll
                for (int v = 0; v < 4; ++v) {
                    acc[u][v] = ffma2(av[u].x, bv[v].x, acc[u][v]);
                    acc[u][v] = ffma2(av[u].y, bv[v].y, acc[u][v]);
                }
        }
        #pragma unroll
        for (int u = 0; u < 2; ++u)
            #pragma unroll
            for (int v = 0; v < 4; ++v) {
                float2 f2 = unpack2(acc[u][v]);
                redw[w * (BS * RB) + (bg + 4 * u) * RB + (ig + 8 * v)] = f2.x + f2.y;
            }
        __syncthreads();                                  // the ONE barrier

        // ---- k-reduce + h update + tanh (critical path, minimal) ----
        float s = 0.f;
        #pragma unroll
        for (int k = 0; k < KW; ++k) s += redw[k * (BS * RB) + b * RB + i];
        h = h * (1.0f - DTC) + DTC * (s + vt * bmv);
        const float th = fast_tanh(h);

        // ---- publish th + RELEASE (nothing else in front of it) ----
        if (t < T_STEPS - 1)
            __stcg(&g_th[p][b0 + b][i0 + i], th);
        __syncwarp();
        fence_gpu();                                      // warp-level release
        if (lane == 0) red_add_gpu(fOwn, 1);

        // ---- post-release: readout partial for row b (needed at t+2) ----
        float c = th * wrv;
        #pragma unroll
        for (int off = 16; off > 0; off >>= 1)
            c += __shfl_xor_sync(0xffffffffu, c, off);
        if (lane == 0)
            __stcg(&g_part[t & 3][grp][rank][b], c);

        // ---- post-release: rotating out-writer (rank t&15, warp 0) ----
        if (t >= 2 && w == 0 && rank == (t & 15)) {
            const float* gp = &g_part[(t - 2) & 3][grp][0][0];  // [NR][BS]
            const int bq = lane >> 2, rq = lane & 3;
            float sres = 0.f;
            #pragma unroll
            for (int k = 0; k < 4; ++k)
                sres += __ldcg(&gp[(rq * 4 + k) * BS + bq]);
            sres += __shfl_xor_sync(0xffffffffu, sres, 1);
            sres += __shfl_xor_sync(0xffffffffu, sres, 2);
            if (rq == 0)
                out[(size_t)(b0 + bq) * T_STEPS + (t - 2)] = sres;
        }
    }

    // ---- extra release round: makes final g_part stores pollable ----
    __syncwarp();
    fence_gpu();
    if (lane == 0) red_add_gpu(fOwn, 1);

    // ---- flush: ranks 0,1 write out[:,1022] and out[:,1023] ----
    if (rank <= 1) {
        if (tid < NR) {
            const int tgt = base + 8 * T_STEPS + 8;
            while (ld_acq(&g_cnt[grp][tid][0]) < tgt) { }
        }
        __syncthreads();
        if (w == 0) {
            const int tf = T_STEPS - 2 + rank;            // 1022 or 1023
            const float* gp = &g_part[tf & 3][grp][0][0];
            const int bq = lane >> 2, rq = lane & 3;
            float sres = 0.f;
            #pragma unroll
            for (int k = 0; k < 4; ++k)
                sres += __ldcg(&gp[(rq * 4 + k) * BS + bq]);
            sres += __shfl_xor_sync(0xffffffffu, sres, 1);
            sres += __shfl_xor_sync(0xffffffffu, sres, 2);
            if (rq == 0)
                out[(size_t)(b0 + bq) * T_STEPS + tf] = sres;
        }
    }
}

extern "C" void kernel_launch(void* const* d_in, const int* in_sizes, int n_in,
                              void* d_out, int out_size) {
    const float* vel  = (const float*)d_in[0];   // [128,1024,1]
    const float* J    = (const float*)d_in[1];   // [512,512]
    const float* Bmat = (const float*)d_in[2];   // [512,1]
    const float* Wro  = (const float*)d_in[3];   // [1,512]
    float* out = (float*)d_out;                  // [128,1024,1]

    cudaFuncSetAttribute(ctrnn_r10_kernel,
                         cudaFuncAttributeMaxDynamicSharedMemorySize, SMEM_BYTES);
    ctrnn_r10_kernel<<<NCTA, NTHR, SMEM_BYTES>>>(vel, J, Bmat, Wro, out);
}